// round 6
// baseline (speedup 1.0000x reference)
#include <cuda_runtime.h>
#include <cuda_bf16.h>
#include <cstddef>
#include <cstdint>

// Problem constants
#define BATCH 8
#define SEQ   1024
#define DIM   1024
#define HEADS 16
#define HDIM  64
#define MROWS (BATCH * SEQ)          // 8192
#define QKVN  (3 * DIM)              // 3072
#define SCALE 0.03125f               // DIM^-0.5 = 1/32
#define MASKV (-3.402823466e38f)
#define NEGINF (-__int_as_float(0x7f800000) * 1.0f)

// Scratch (static device globals: allocation-free rule)
__device__ float g_q[BATCH * HEADS * SEQ * HDIM];     // [b,h,n,d]  (tf32-rounded)
__device__ float g_k[BATCH * HEADS * SEQ * HDIM];
__device__ float g_v[BATCH * HEADS * SEQ * HDIM];
__device__ float g_attn[BATCH * SEQ * DIM];           // [b,n,h*d]  (tf32-rounded)
// tf32-rounded input copies (rounding hoisted out of GEMM hot loops)
__device__ float g_xr[MROWS * DIM];
__device__ float g_wqkr[2 * DIM * DIM];
__device__ float g_wvr[DIM * DIM];
__device__ float g_woutr[DIM * DIM];

// ---------------------------------------------------------------------------
// helpers
// ---------------------------------------------------------------------------
__device__ __forceinline__ float tf32_rna(float x) {
    uint32_t u;
    asm("cvt.rna.tf32.f32 %0, %1;" : "=r"(u) : "f"(x));
    return __uint_as_float(u);
}

__device__ __forceinline__ void mma_tf32_16x8x8(float* c, const float* a, const float* b) {
    asm volatile(
        "mma.sync.aligned.m16n8k8.row.col.f32.tf32.tf32.f32 "
        "{%0,%1,%2,%3}, {%4,%5,%6,%7}, {%8,%9}, {%0,%1,%2,%3};"
        : "+f"(c[0]), "+f"(c[1]), "+f"(c[2]), "+f"(c[3])
        : "r"(__float_as_uint(a[0])), "r"(__float_as_uint(a[1])),
          "r"(__float_as_uint(a[2])), "r"(__float_as_uint(a[3])),
          "r"(__float_as_uint(b[0])), "r"(__float_as_uint(b[1])));
}

__device__ __forceinline__ void cp16(void* smem, const void* g) {
    uint32_t s = (uint32_t)__cvta_generic_to_shared(smem);
    asm volatile("cp.async.cg.shared.global [%0], [%1], 16;" :: "r"(s), "l"(g));
}
__device__ __forceinline__ void cp_commit() {
    asm volatile("cp.async.commit_group;");
}

// ---------------------------------------------------------------------------
// Kernel 0: round fp32 -> tf32-valued fp32 (vectorized)
// ---------------------------------------------------------------------------
__global__ __launch_bounds__(256) void round_kernel(
    const float4* __restrict__ src, float4* __restrict__ dst, int n4)
{
    int i = blockIdx.x * 256 + threadIdx.x;
    if (i < n4) {
        float4 v = src[i];
        v.x = tf32_rna(v.x); v.y = tf32_rna(v.y);
        v.z = tf32_rna(v.z); v.w = tf32_rna(v.w);
        dst[i] = v;
    }
}

// ---------------------------------------------------------------------------
// tf32 GEMM core, cp.async 2-stage pipeline. 128x128 tile, K-tile 32,
// 256 threads, 8 warps (2M x 4N), warp tile 64x32 via m16n8k8.
// Inputs must already be tf32-valued.
// ---------------------------------------------------------------------------
#define TPAD 36   // row stride 144 B (16B-aligned, bank-permuting)

struct GemmAcc { float acc[4][4][4]; };

__device__ __forceinline__ void gemm_core_async(
    const float* __restrict__ Abase, const float* __restrict__ B0,
    const float* __restrict__ B1, int bm, int bn, bool splitB,
    float* sm, GemmAcc& g)
{
    // layout: As[2][128][TPAD], Bs[2][128][TPAD]
    float (*As)[128][TPAD] = (float(*)[128][TPAD])sm;
    float (*Bs)[128][TPAD] = (float(*)[128][TPAD])(sm + 2 * 128 * TPAD);

    const int tid = threadIdx.x;
    const int lane = tid & 31;
    const int wid = tid >> 5;
    const int gid = lane >> 2, tg = lane & 3;
    const int wm = (wid & 1) * 64;
    const int wn = (wid >> 1) * 32;

#pragma unroll
    for (int mi = 0; mi < 4; mi++)
#pragma unroll
        for (int ni = 0; ni < 4; ni++)
#pragma unroll
            for (int r = 0; r < 4; r++) g.acc[mi][ni][r] = 0.f;

    auto load_tiles = [&](int st, int k0) {
#pragma unroll
        for (int i = tid; i < 128 * 8; i += 256) {
            int row = i >> 3, c4 = (i & 7) * 4;
            cp16(&As[st][row][c4], &Abase[(size_t)(bm + row) * DIM + k0 + c4]);
        }
#pragma unroll
        for (int i = tid; i < 128 * 8; i += 256) {
            int row = i >> 3, c4 = (i & 7) * 4;
            int gn = bn + row;
            const float* Brow = (splitB && gn >= 2 * DIM)
                                ? B1 + (size_t)(gn - 2 * DIM) * DIM
                                : B0 + (size_t)gn * DIM;
            cp16(&Bs[st][row][c4], &Brow[k0 + c4]);
        }
    };

    load_tiles(0, 0);
    cp_commit();

    const int NT = DIM / 32;  // 32
    for (int it = 0; it < NT; it++) {
        int cur = it & 1;
        if (it + 1 < NT) {
            load_tiles(cur ^ 1, (it + 1) * 32);
            cp_commit();
            asm volatile("cp.async.wait_group 1;");
        } else {
            asm volatile("cp.async.wait_group 0;");
        }
        __syncthreads();

#pragma unroll
        for (int ks = 0; ks < 32; ks += 8) {
            float a[4][4];
#pragma unroll
            for (int mi = 0; mi < 4; mi++) {
                int r0 = wm + mi * 16 + gid;
                a[mi][0] = As[cur][r0][ks + tg];
                a[mi][1] = As[cur][r0 + 8][ks + tg];
                a[mi][2] = As[cur][r0][ks + tg + 4];
                a[mi][3] = As[cur][r0 + 8][ks + tg + 4];
            }
            float b[4][2];
#pragma unroll
            for (int ni = 0; ni < 4; ni++) {
                int n0 = wn + ni * 8 + gid;
                b[ni][0] = Bs[cur][n0][ks + tg];
                b[ni][1] = Bs[cur][n0][ks + tg + 4];
            }
#pragma unroll
            for (int mi = 0; mi < 4; mi++)
#pragma unroll
                for (int ni = 0; ni < 4; ni++)
                    mma_tf32_16x8x8(g.acc[mi][ni], a[mi], b[ni]);
        }
        __syncthreads();
    }
}

#define GEMM_SMEM_BYTES (4 * 128 * TPAD * 4)   // 73728

// ---------------------------------------------------------------------------
// Kernel 1: fused QKV projection. Epilogue adds pos (fp32), rounds result to
// tf32 (feeds attention MMAs), scatters to [b,h,n,d].
// ---------------------------------------------------------------------------
__global__ __launch_bounds__(256) void qkv_gemm_kernel(const float* __restrict__ pos)
{
    extern __shared__ float sm[];
    const int bm = blockIdx.y * 128;
    const int bn = blockIdx.x * 128;
    const int lane = threadIdx.x & 31;
    const int wid = threadIdx.x >> 5;
    const int gid = lane >> 2, tg = lane & 3;
    const int wm = (wid & 1) * 64;
    const int wn = (wid >> 1) * 32;

    GemmAcc g;
    gemm_core_async(g_xr, g_wqkr, g_wvr, bm, bn, true, sm, g);

#pragma unroll
    for (int mi = 0; mi < 4; mi++) {
#pragma unroll
        for (int ni = 0; ni < 4; ni++) {
#pragma unroll
            for (int r = 0; r < 4; r++) {
                int m = bm + wm + mi * 16 + gid + ((r >= 2) ? 8 : 0);
                int gn = bn + wn + ni * 8 + 2 * tg + (r & 1);
                int b = m >> 10, row = m & 1023;
                float val = g.acc[mi][ni][r];
                if (gn < DIM) {
                    int c = gn, h = c >> 6, d = c & 63;
                    val = tf32_rna(val + pos[(size_t)m * DIM + c]);
                    g_q[(((size_t)b * HEADS + h) * SEQ + row) * HDIM + d] = val;
                } else if (gn < 2 * DIM) {
                    int c = gn - DIM, h = c >> 6, d = c & 63;
                    val = tf32_rna(val + pos[(size_t)m * DIM + c]);
                    g_k[(((size_t)b * HEADS + h) * SEQ + row) * HDIM + d] = val;
                } else {
                    int c = gn - 2 * DIM, h = c >> 6, d = c & 63;
                    g_v[(((size_t)b * HEADS + h) * SEQ + row) * HDIM + d] = tf32_rna(val);
                }
            }
        }
    }
}

// ---------------------------------------------------------------------------
// Kernel 3: output projection. out = g_attn @ W_out^T + b_out (fp32 epilogue)
// ---------------------------------------------------------------------------
__global__ __launch_bounds__(256) void out_gemm_kernel(
    const float* __restrict__ bout, float* __restrict__ out)
{
    extern __shared__ float sm[];
    const int bm = blockIdx.y * 128;
    const int bn = blockIdx.x * 128;
    const int lane = threadIdx.x & 31;
    const int wid = threadIdx.x >> 5;
    const int gid = lane >> 2, tg = lane & 3;
    const int wm = (wid & 1) * 64;
    const int wn = (wid >> 1) * 32;

    GemmAcc g;
    gemm_core_async(g_attn, g_woutr, nullptr, bm, bn, false, sm, g);

#pragma unroll
    for (int mi = 0; mi < 4; mi++) {
#pragma unroll
        for (int ni = 0; ni < 4; ni++) {
#pragma unroll
            for (int r = 0; r < 4; r++) {
                int m = bm + wm + mi * 16 + gid + ((r >= 2) ? 8 : 0);
                int gn = bn + wn + ni * 8 + 2 * tg + (r & 1);
                out[(size_t)m * DIM + gn] = g.acc[mi][ni][r] + bout[gn];
            }
        }
    }
}

// ---------------------------------------------------------------------------
// Kernel 2: tensor-core flash attention with cp.async double-buffered K/V.
// 128 query rows per CTA, 8 warps, each owns 16 rows; j-tiles of 64 keys.
// Q fragments register-resident. S and PV via m16n8k8 tf32. Online softmax in
// registers (quad shfl reduce). P staged through smem overlaid on the dead Q
// tile (warp-private rows). Ks stride 68 (bank 4*gid+tg perm), Vs stride 72
// (bank 8*tg+gid perm) -> both fragment patterns conflict-free.
// ---------------------------------------------------------------------------
#define AKPAD 68
#define AVPAD 72
#define ATT_SMEM_FLOATS (128 * AKPAD + 2 * 64 * AKPAD + 2 * 64 * AVPAD + 2 * 64)
#define ATT_SMEM_BYTES  (ATT_SMEM_FLOATS * 4)   // 107008

__global__ __launch_bounds__(256) void attn_kernel(const int* __restrict__ mask)
{
    extern __shared__ float sm[];
    float (*QP)[AKPAD]  = (float(*)[AKPAD])sm;                       // Q tile, later P
    float (*KsB)[AKPAD] = (float(*)[AKPAD])(sm + 128 * AKPAD);      // [2*64][AKPAD]
    float (*VsB)[AVPAD] = (float(*)[AVPAD])(sm + 128 * AKPAD + 2 * 64 * AKPAD);
    float* kmB = sm + 128 * AKPAD + 2 * 64 * AKPAD + 2 * 64 * AVPAD; // [2][64]

    const int bh = blockIdx.y;
    const int b = bh >> 4, h = bh & 15;
    const int i0 = blockIdx.x * 128;
    const int tid = threadIdx.x;
    const int lane = tid & 31, wid = tid >> 5;
    const int gid = lane >> 2, tg = lane & 3;
    const int r0 = wid * 16 + gid;
    const int r1 = r0 + 8;

    const float* qb = g_q + ((size_t)bh * SEQ + i0) * HDIM;
    const float* kb = g_k + (size_t)bh * SEQ * HDIM;
    const float* vb = g_v + (size_t)bh * SEQ * HDIM;

    auto load_kv = [&](int st, int j0) {
        float (*K)[AKPAD] = KsB + st * 64;
        float (*V)[AVPAD] = VsB + st * 64;
#pragma unroll
        for (int i = tid; i < 64 * 16; i += 256) {
            int row = i >> 4, c4 = (i & 15) * 4;
            cp16(&K[row][c4], &kb[(size_t)(j0 + row) * HDIM + c4]);
            cp16(&V[row][c4], &vb[(size_t)(j0 + row) * HDIM + c4]);
        }
    };
    auto load_km = [&](int st, int j0) {
        if (tid < 64) {
            int gj = j0 + tid;
            kmB[st * 64 + tid] =
                (gj == 0) ? 1.f : (mask[(size_t)b * (SEQ - 1) + gj - 1] ? 1.f : 0.f);
        }
    };

    // kick off tile 0 K/V while we stage Q
    load_kv(0, 0);
    cp_commit();
    load_km(0, 0);

    // stage Q (already tf32-valued)
    for (int i = tid; i < 128 * 16; i += 256) {
        int row = i >> 4, c4 = (i & 15) * 4;
        *(float4*)&QP[row][c4] = *(const float4*)&qb[(size_t)row * HDIM + c4];
    }
    __syncthreads();

    // Q fragments to registers (held across the whole key loop)
    float qa[8][4];
#pragma unroll
    for (int ks = 0; ks < 8; ks++) {
        qa[ks][0] = QP[r0][ks * 8 + tg];
        qa[ks][1] = QP[r1][ks * 8 + tg];
        qa[ks][2] = QP[r0][ks * 8 + tg + 4];
        qa[ks][3] = QP[r1][ks * 8 + tg + 4];
    }
    const int gi0 = i0 + r0, gi1 = i0 + r1;
    const bool qok0 = (gi0 == 0) || (mask[(size_t)b * (SEQ - 1) + gi0 - 1] != 0);
    const bool qok1 = (gi1 == 0) || (mask[(size_t)b * (SEQ - 1) + gi1 - 1] != 0);

    float m0 = NEGINF, m1 = NEGINF, l0 = 0.f, l1 = 0.f;
    float o[8][4] = {};

    const int NT = SEQ / 64;   // 16
    for (int it = 0; it < NT; it++) {
        const int cur = it & 1;
        if (it + 1 < NT) {
            load_kv(cur ^ 1, (it + 1) * 64);
            cp_commit();
            load_km(cur ^ 1, (it + 1) * 64);
            asm volatile("cp.async.wait_group 1;");
        } else {
            asm volatile("cp.async.wait_group 0;");
        }
        __syncthreads();

        float (*Ks)[AKPAD] = KsB + cur * 64;
        float (*Vs)[AVPAD] = VsB + cur * 64;
        const float* km = kmB + cur * 64;

        // S = Q K^T  (16 rows x 64 keys per warp)
        float s[8][4] = {};
#pragma unroll
        for (int ks = 0; ks < 8; ks++) {
#pragma unroll
            for (int ni = 0; ni < 8; ni++) {
                float bf[2] = { Ks[ni * 8 + gid][ks * 8 + tg],
                                Ks[ni * 8 + gid][ks * 8 + tg + 4] };
                mma_tf32_16x8x8(s[ni], qa[ks], bf);
            }
        }

        // mask + scale + row max
        float rmax0 = NEGINF, rmax1 = NEGINF;
#pragma unroll
        for (int ni = 0; ni < 8; ni++) {
            bool k0ok = km[ni * 8 + 2 * tg] != 0.f;
            bool k1ok = km[ni * 8 + 2 * tg + 1] != 0.f;
            s[ni][0] = (qok0 && k0ok) ? s[ni][0] * SCALE : MASKV;
            s[ni][1] = (qok0 && k1ok) ? s[ni][1] * SCALE : MASKV;
            s[ni][2] = (qok1 && k0ok) ? s[ni][2] * SCALE : MASKV;
            s[ni][3] = (qok1 && k1ok) ? s[ni][3] * SCALE : MASKV;
            rmax0 = fmaxf(rmax0, fmaxf(s[ni][0], s[ni][1]));
            rmax1 = fmaxf(rmax1, fmaxf(s[ni][2], s[ni][3]));
        }
        rmax0 = fmaxf(rmax0, __shfl_xor_sync(0xffffffffu, rmax0, 1));
        rmax0 = fmaxf(rmax0, __shfl_xor_sync(0xffffffffu, rmax0, 2));
        rmax1 = fmaxf(rmax1, __shfl_xor_sync(0xffffffffu, rmax1, 1));
        rmax1 = fmaxf(rmax1, __shfl_xor_sync(0xffffffffu, rmax1, 2));

        float nm0 = fmaxf(m0, rmax0), nm1 = fmaxf(m1, rmax1);
        float fac0 = __expf(m0 - nm0), fac1 = __expf(m1 - nm1);
        m0 = nm0; m1 = nm1;

        // P = exp(S - m), tf32-rounded; sum rows; stage to smem (Q overlay)
        float sum0 = 0.f, sum1 = 0.f;
#pragma unroll
        for (int ni = 0; ni < 8; ni++) {
            float p0 = tf32_rna(__expf(s[ni][0] - m0));
            float p1 = tf32_rna(__expf(s[ni][1] - m0));
            float p2 = tf32_rna(__expf(s[ni][2] - m1));
            float p3 = tf32_rna(__expf(s[ni][3] - m1));
            sum0 += p0 + p1; sum1 += p2 + p3;
            QP[r0][ni * 8 + 2 * tg]     = p0;
            QP[r0][ni * 8 + 2 * tg + 1] = p1;
            QP[r1][ni * 8 + 2 * tg]     = p2;
            QP[r1][ni * 8 + 2 * tg + 1] = p3;
        }
        sum0 += __shfl_xor_sync(0xffffffffu, sum0, 1);
        sum0 += __shfl_xor_sync(0xffffffffu, sum0, 2);
        sum1 += __shfl_xor_sync(0xffffffffu, sum1, 1);
        sum1 += __shfl_xor_sync(0xffffffffu, sum1, 2);
        l0 = l0 * fac0 + sum0;
        l1 = l1 * fac1 + sum1;

#pragma unroll
        for (int ni = 0; ni < 8; ni++) {
            o[ni][0] *= fac0; o[ni][1] *= fac0;
            o[ni][2] *= fac1; o[ni][3] *= fac1;
        }
        __syncwarp();   // P writes visible to the whole warp before PV reads

        // O += P V   (k-dim = 64 keys)
#pragma unroll
        for (int ks = 0; ks < 8; ks++) {
            float pa[4] = { QP[r0][ks * 8 + tg], QP[r1][ks * 8 + tg],
                            QP[r0][ks * 8 + tg + 4], QP[r1][ks * 8 + tg + 4] };
#pragma unroll
            for (int ni = 0; ni < 8; ni++) {
                float bf[2] = { Vs[ks * 8 + tg][ni * 8 + gid],
                                Vs[ks * 8 + tg + 4][ni * 8 + gid] };
                mma_tf32_16x8x8(o[ni], pa, bf);
            }
        }
        __syncthreads();   // all reads done before next iter's cp.async overwrites
    }

    // normalize + write (tf32-rounded: feeds the cp.async out GEMM)
    float inv0 = 1.f / l0, inv1 = 1.f / l1;
    size_t row0 = (size_t)b * SEQ + i0 + r0;
    size_t row1 = (size_t)b * SEQ + i0 + r1;
#pragma unroll
    for (int ni = 0; ni < 8; ni++) {
        float2 v0 = { tf32_rna(o[ni][0] * inv0), tf32_rna(o[ni][1] * inv0) };
        float2 v1 = { tf32_rna(o[ni][2] * inv1), tf32_rna(o[ni][3] * inv1) };
        *(float2*)&g_attn[row0 * DIM + h * HDIM + ni * 8 + 2 * tg] = v0;
        *(float2*)&g_attn[row1 * DIM + h * HDIM + ni * 8 + 2 * tg] = v1;
    }
}

// ---------------------------------------------------------------------------
extern "C" void kernel_launch(void* const* d_in, const int* in_sizes, int n_in,
                              void* d_out, int out_size)
{
    const float* x    = (const float*)d_in[0];
    const int*   mask = (const int*)d_in[1];     // bool widened to int32 by harness
    const float* pos  = (const float*)d_in[2];
    const float* Wqk  = (const float*)d_in[3];
    const float* Wv   = (const float*)d_in[4];
    const float* Wout = (const float*)d_in[5];
    const float* bout = (const float*)d_in[6];
    float*       out  = (float*)d_out;

    cudaFuncSetAttribute(qkv_gemm_kernel, cudaFuncAttributeMaxDynamicSharedMemorySize,
                         GEMM_SMEM_BYTES);
    cudaFuncSetAttribute(out_gemm_kernel, cudaFuncAttributeMaxDynamicSharedMemorySize,
                         GEMM_SMEM_BYTES);
    cudaFuncSetAttribute(attn_kernel, cudaFuncAttributeMaxDynamicSharedMemorySize,
                         ATT_SMEM_BYTES);

    float* d_xr; float* d_wqkr; float* d_wvr; float* d_woutr;
    cudaGetSymbolAddress((void**)&d_xr,    g_xr);
    cudaGetSymbolAddress((void**)&d_wqkr,  g_wqkr);
    cudaGetSymbolAddress((void**)&d_wvr,   g_wvr);
    cudaGetSymbolAddress((void**)&d_woutr, g_woutr);

    {   // prep: round inputs to tf32 once
        int n4;
        n4 = MROWS * DIM / 4;
        round_kernel<<<(n4 + 255) / 256, 256>>>((const float4*)x, (float4*)d_xr, n4);
        n4 = 2 * DIM * DIM / 4;
        round_kernel<<<(n4 + 255) / 256, 256>>>((const float4*)Wqk, (float4*)d_wqkr, n4);
        n4 = DIM * DIM / 4;
        round_kernel<<<(n4 + 255) / 256, 256>>>((const float4*)Wv, (float4*)d_wvr, n4);
        round_kernel<<<(n4 + 255) / 256, 256>>>((const float4*)Wout, (float4*)d_woutr, n4);
    }
    {   // QKV projection: M=8192, N=3072
        dim3 grid(QKVN / 128, MROWS / 128);
        qkv_gemm_kernel<<<grid, 256, GEMM_SMEM_BYTES>>>(pos);
    }
    {   // Attention: 8 row-tiles x 128 (b,h) pairs
        dim3 grid(SEQ / 128, BATCH * HEADS);
        attn_kernel<<<grid, 256, ATT_SMEM_BYTES>>>(mask);
    }
    {   // Output projection: M=8192, N=1024
        dim3 grid(DIM / 128, MROWS / 128);
        out_gemm_kernel<<<grid, 256, GEMM_SMEM_BYTES>>>(bout, out);
    }
}